// round 6
// baseline (speedup 1.0000x reference)
#include <cuda_runtime.h>
#include <math.h>

#define BGRAPH 64
#define NNODE  1024
#define FDIM   128
#define NUM    (BGRAPH*NNODE)
#define NE     2097152
#define KSEL   4

__device__ float d_xn  [NUM*FDIM];
__device__ float d_hf  [NUM*FDIM];
__device__ float d_hs  [NUM*FDIM];
__device__ float d_feat[NUM*FDIM];
__device__ float d_stru[NUM*FDIM];
__device__ float d_gate[NUM*FDIM];
__device__ int   d_topk[NUM*KSEL];
__device__ int   d_cntf[NUM];
__device__ int   d_cnts[NUM];
__device__ int   d_offf[NUM];
__device__ int   d_offs[NUM];
__device__ int   d_fillf[NUM];
__device__ int   d_fills[NUM];
__device__ float d_dinvf[NUM];
__device__ float d_dinvs[NUM];
__device__ int   d_csrf[NUM*KSEL];
__device__ int   d_csrs[NE];

typedef unsigned long long ull;

__device__ __forceinline__ void ffma2(ull& d, ull a, ull b) {
    asm("fma.rn.f32x2 %0, %1, %2, %0;" : "+l"(d) : "l"(a), "l"(b));
}
__device__ __forceinline__ ull dup2(float v) {
    ull r;
    asm("mov.b64 %0, {%1, %1};" : "=l"(r) : "f"(v));
    return r;
}
__device__ __forceinline__ float2 unpack2(ull v) {
    float2 f;
    asm("mov.b64 {%0, %1}, %2;" : "=f"(f.x), "=f"(f.y) : "l"(v));
    return f;
}

__device__ __forceinline__ float warp_sum(float v) {
#pragma unroll
    for (int o = 16; o > 0; o >>= 1) v += __shfl_xor_sync(0xffffffffu, v, o);
    return v;
}

__device__ __forceinline__ void ins4(ull& k0, ull& k1, ull& k2, ull& k3, ull c) {
    if (c < k3) {
        k3 = c;
        if (k3 < k2) { ull t = k2; k2 = k3; k3 = t; }
        if (k2 < k1) { ull t = k1; k1 = k2; k2 = t; }
        if (k1 < k0) { ull t = k0; k0 = k1; k1 = t; }
    }
}

// 1) row-normalize x
__global__ void knorm(const float* __restrict__ x) {
    int row = blockIdx.x, t = threadIdx.x;
    float v = x[row * FDIM + t];
    float ss = warp_sum(v * v);
    __shared__ float sh[4];
    if ((t & 31) == 0) sh[t >> 5] = ss;
    __syncthreads();
    float tot = sh[0] + sh[1] + sh[2] + sh[3];
    float den = fmaxf(sqrtf(tot), 1e-8f);
    d_xn[row * FDIM + t] = v / den;
}

// 2) zero counters
__global__ void kinit() {
    int i = blockIdx.x * blockDim.x + threadIdx.x;
    if (i < NUM) { d_cntf[i] = 0; d_cnts[i] = 0; d_fillf[i] = 0; d_fills[i] = 0; }
}

// 3) structural in-degree
__global__ void kcnt_s(const int* __restrict__ ei) {
    int e = blockIdx.x * blockDim.x + threadIdx.x;
    if (e < NE) atomicAdd(&d_cnts[ei[NE + e]], 1);
}

// 4) all-pairs cosine + top-4 farthest, FFMA2 inner loop.
// thread's 8 cols = {tx*4..tx*4+3, 64+tx*4..64+tx*4+3} (conflict-free LDS.128)
__global__ void __launch_bounds__(256) ktopk() {
    __shared__ __align__(16) float As[32 * 68];
    __shared__ __align__(16) float Bs[32 * 132];
    const int g = blockIdx.y;
    const int rowbase = blockIdx.x * 64;
    const int t = threadIdx.x, tx = t & 15, ty = t >> 4;
    const float* xg = d_xn + (size_t)g * NNODE * FDIM;

    ull tkA[4], tkB[4], tkC[4], tkD[4];
#pragma unroll
    for (int ri = 0; ri < 4; ri++) { tkA[ri]=tkB[ri]=tkC[ri]=tkD[ri]=0xffffffffffffffffull; }

    for (int cc = 0; cc < 8; cc++) {
        ull acc2[4][4];
#pragma unroll
        for (int ri = 0; ri < 4; ri++)
#pragma unroll
            for (int cj = 0; cj < 4; cj++) acc2[ri][cj] = 0ull;

        for (int kc = 0; kc < 4; kc++) {
            __syncthreads();
#pragma unroll
            for (int j = 0; j < 2; j++) {
                int idx = t + j * 256;
                int r = idx >> 3, k4 = idx & 7;
                float4 v = *(const float4*)&xg[(rowbase + r) * FDIM + kc * 32 + k4 * 4];
                As[(k4 * 4 + 0) * 68 + r] = v.x; As[(k4 * 4 + 1) * 68 + r] = v.y;
                As[(k4 * 4 + 2) * 68 + r] = v.z; As[(k4 * 4 + 3) * 68 + r] = v.w;
            }
#pragma unroll
            for (int j = 0; j < 4; j++) {
                int idx = t + j * 256;
                int c = idx >> 3, k4 = idx & 7;
                float4 v = *(const float4*)&xg[(cc * 128 + c) * FDIM + kc * 32 + k4 * 4];
                Bs[(k4 * 4 + 0) * 132 + c] = v.x; Bs[(k4 * 4 + 1) * 132 + c] = v.y;
                Bs[(k4 * 4 + 2) * 132 + c] = v.z; Bs[(k4 * 4 + 3) * 132 + c] = v.w;
            }
            __syncthreads();
#pragma unroll 8
            for (int k = 0; k < 32; k++) {
                float4 a = *(const float4*)&As[k * 68 + ty * 4];
                ulonglong2 bb0 = *(const ulonglong2*)&Bs[k * 132 + tx * 4];
                ulonglong2 bb1 = *(const ulonglong2*)&Bs[k * 132 + 64 + tx * 4];
                ull ap[4] = {dup2(a.x), dup2(a.y), dup2(a.z), dup2(a.w)};
#pragma unroll
                for (int ri = 0; ri < 4; ri++) {
                    ffma2(acc2[ri][0], ap[ri], bb0.x);
                    ffma2(acc2[ri][1], ap[ri], bb0.y);
                    ffma2(acc2[ri][2], ap[ri], bb1.x);
                    ffma2(acc2[ri][3], ap[ri], bb1.y);
                }
            }
        }
#pragma unroll
        for (int ri = 0; ri < 4; ri++)
#pragma unroll
            for (int cj = 0; cj < 4; cj++) {
                float2 p = unpack2(acc2[ri][cj]);
                int col0 = cc * 128 + ((cj < 2) ? (tx * 4 + cj * 2) : (64 + tx * 4 + (cj - 2) * 2));
#pragma unroll
                for (int h = 0; h < 2; h++) {
                    float dval = 1.0f - ((h == 0) ? p.x : p.y);
                    unsigned u = __float_as_uint(dval);
                    u = (u & 0x80000000u) ? ~u : (u | 0x80000000u);
                    ull key = (((ull)(~u)) << 10) | (ull)(col0 + h);
                    ins4(tkA[ri], tkB[ri], tkC[ri], tkD[ri], key);
                }
            }
    }
#pragma unroll
    for (int off = 8; off > 0; off >>= 1) {
#pragma unroll
        for (int ri = 0; ri < 4; ri++) {
            ull c0 = __shfl_down_sync(0xffffffffu, tkA[ri], off, 16);
            ull c1 = __shfl_down_sync(0xffffffffu, tkB[ri], off, 16);
            ull c2 = __shfl_down_sync(0xffffffffu, tkC[ri], off, 16);
            ull c3 = __shfl_down_sync(0xffffffffu, tkD[ri], off, 16);
            if (tx < off) {
                ins4(tkA[ri], tkB[ri], tkC[ri], tkD[ri], c0);
                ins4(tkA[ri], tkB[ri], tkC[ri], tkD[ri], c1);
                ins4(tkA[ri], tkB[ri], tkC[ri], tkD[ri], c2);
                ins4(tkA[ri], tkB[ri], tkC[ri], tkD[ri], c3);
            }
        }
    }
    if (tx == 0) {
#pragma unroll
        for (int ri = 0; ri < 4; ri++) {
            int grow = g * NNODE + rowbase + ty * 4 + ri;
            ull ks[4] = {tkA[ri], tkB[ri], tkC[ri], tkD[ri]};
#pragma unroll
            for (int q = 0; q < 4; q++) {
                int j  = (int)(ks[q] & 1023ull);
                int dg = g * NNODE + j;
                d_topk[grow * 4 + q] = dg;
                atomicAdd(&d_cntf[dg], 1);
            }
        }
    }
}

// 5) exclusive scans (block 0 = feature counts, block 1 = structural)
__global__ void kscan() {
    int which = blockIdx.x;
    const int* cnt = which ? d_cnts : d_cntf;
    int* off = which ? d_offs : d_offf;
    __shared__ int sh[1024];
    int t = threadIdx.x;
    int base = t * 64;
    int sum = 0;
    for (int i = 0; i < 64; i++) sum += cnt[base + i];
    sh[t] = sum;
    __syncthreads();
    for (int o = 1; o < 1024; o <<= 1) {
        int v = (t >= o) ? sh[t - o] : 0;
        __syncthreads();
        sh[t] += v;
        __syncthreads();
    }
    int run = sh[t] - sum;
    for (int i = 0; i < 64; i++) { int c = cnt[base + i]; off[base + i] = run; run += c; }
}

// 6) dinv = rsqrt(deg) incl. self-loop
__global__ void kdinv() {
    int i = blockIdx.x * blockDim.x + threadIdx.x;
    if (i < NUM) {
        d_dinvf[i] = rsqrtf((float)(d_cntf[i] + 1));
        d_dinvs[i] = rsqrtf((float)(d_cnts[i] + 1));
    }
}

// 7) CSR fill
__global__ void kfill_f() {
    int e = blockIdx.x * blockDim.x + threadIdx.x;
    if (e < NUM * KSEL) {
        int srcn = e >> 2;
        int dg = d_topk[e];
        int pos = d_offf[dg] + atomicAdd(&d_fillf[dg], 1);
        d_csrf[pos] = srcn;
    }
}
__global__ void kfill_s(const int* __restrict__ ei) {
    int e = blockIdx.x * blockDim.x + threadIdx.x;
    if (e < NE) {
        int s = ei[e], dg = ei[NE + e];
        int pos = d_offs[dg] + atomicAdd(&d_fills[dg], 1);
        d_csrs[pos] = s;
    }
}

// 8) h = x @ W (z: 0=feat, 1=stru), FFMA2 inner loop
__global__ void __launch_bounds__(256) kgemm_h(const float* __restrict__ x,
                                               const float* __restrict__ Wf,
                                               const float* __restrict__ Wst) {
    const float* W = blockIdx.z ? Wst : Wf;
    float* out = blockIdx.z ? d_hs : d_hf;
    __shared__ __align__(16) float As[32 * 68];
    __shared__ __align__(16) float Bs[32 * 132];
    int t = threadIdx.x, tx = t & 15, ty = t >> 4;
    int rowbase = blockIdx.x * 64;
    ull acc2[4][4];
#pragma unroll
    for (int ri = 0; ri < 4; ri++)
#pragma unroll
        for (int cj = 0; cj < 4; cj++) acc2[ri][cj] = 0ull;

    for (int kc = 0; kc < 4; kc++) {
        __syncthreads();
#pragma unroll
        for (int j = 0; j < 2; j++) {
            int idx = t + j * 256;
            int r = idx >> 3, k4 = idx & 7;
            float4 v = *(const float4*)&x[(rowbase + r) * FDIM + kc * 32 + k4 * 4];
            As[(k4 * 4 + 0) * 68 + r] = v.x; As[(k4 * 4 + 1) * 68 + r] = v.y;
            As[(k4 * 4 + 2) * 68 + r] = v.z; As[(k4 * 4 + 3) * 68 + r] = v.w;
        }
#pragma unroll
        for (int j = 0; j < 4; j++) {
            int idx = t + j * 256;
            int kk = idx >> 5, c4 = idx & 31;
            *(float4*)&Bs[kk * 132 + c4 * 4] = *(const float4*)&W[(kc * 32 + kk) * FDIM + c4 * 4];
        }
        __syncthreads();
#pragma unroll 8
        for (int k = 0; k < 32; k++) {
            float4 a = *(const float4*)&As[k * 68 + ty * 4];
            ulonglong2 bb0 = *(const ulonglong2*)&Bs[k * 132 + tx * 4];
            ulonglong2 bb1 = *(const ulonglong2*)&Bs[k * 132 + 64 + tx * 4];
            ull ap[4] = {dup2(a.x), dup2(a.y), dup2(a.z), dup2(a.w)};
#pragma unroll
            for (int ri = 0; ri < 4; ri++) {
                ffma2(acc2[ri][0], ap[ri], bb0.x);
                ffma2(acc2[ri][1], ap[ri], bb0.y);
                ffma2(acc2[ri][2], ap[ri], bb1.x);
                ffma2(acc2[ri][3], ap[ri], bb1.y);
            }
        }
    }
#pragma unroll
    for (int ri = 0; ri < 4; ri++) {
        int row = rowbase + ty * 4 + ri;
        ulonglong2 s0; s0.x = acc2[ri][0]; s0.y = acc2[ri][1];
        ulonglong2 s1; s1.x = acc2[ri][2]; s1.y = acc2[ri][3];
        *(ulonglong2*)&out[row * FDIM + tx * 4] = s0;
        *(ulonglong2*)&out[row * FDIM + 64 + tx * 4] = s1;
    }
}

// 9) GCN aggregate + bias + relu + layernorm (one warp per node)
__global__ void kagg(int which, const float* __restrict__ bias,
                     const float* __restrict__ gamma, const float* __restrict__ beta) {
    int d = (blockIdx.x * blockDim.x + threadIdx.x) >> 5;
    int lane = threadIdx.x & 31;
    const int* off = which ? d_offs : d_offf;
    const int* cnt = which ? d_cnts : d_cntf;
    const int* csr = which ? d_csrs : d_csrf;
    const float* dinv = which ? d_dinvs : d_dinvf;
    const float4* h4 = which ? (const float4*)d_hs : (const float4*)d_hf;
    float* outp = which ? d_stru : d_feat;

    int st = off[d], n = cnt[d];
    float dd = dinv[d];
    float ax = 0.f, ay = 0.f, az = 0.f, aw = 0.f;
    int e = 0;
    for (; e + 4 <= n; e += 4) {
        int s0 = csr[st+e], s1 = csr[st+e+1], s2 = csr[st+e+2], s3 = csr[st+e+3];
        float w0 = dinv[s0]*dd, w1 = dinv[s1]*dd, w2 = dinv[s2]*dd, w3 = dinv[s3]*dd;
        float4 v0 = h4[s0*32+lane], v1 = h4[s1*32+lane];
        float4 v2 = h4[s2*32+lane], v3 = h4[s3*32+lane];
        ax += v0.x*w0 + v1.x*w1 + v2.x*w2 + v3.x*w3;
        ay += v0.y*w0 + v1.y*w1 + v2.y*w2 + v3.y*w3;
        az += v0.z*w0 + v1.z*w1 + v2.z*w2 + v3.z*w3;
        aw += v0.w*w0 + v1.w*w1 + v2.w*w2 + v3.w*w3;
    }
    for (; e < n; e++) {
        int s = csr[st + e];
        float wg = dinv[s] * dd;
        float4 v = h4[s*32+lane];
        ax += v.x*wg; ay += v.y*wg; az += v.z*wg; aw += v.w*wg;
    }
    {
        float4 v = h4[d*32+lane];
        float wg = dd * dd;
        ax += v.x*wg; ay += v.y*wg; az += v.z*wg; aw += v.w*wg;
    }
    float4 b4 = ((const float4*)bias)[lane];
    ax = fmaxf(ax + b4.x, 0.f); ay = fmaxf(ay + b4.y, 0.f);
    az = fmaxf(az + b4.z, 0.f); aw = fmaxf(aw + b4.w, 0.f);
    float mean = warp_sum(ax + ay + az + aw) * (1.0f / 128.0f);
    float dx = ax - mean, dy = ay - mean, dz = az - mean, dw = aw - mean;
    float var = warp_sum(dx*dx + dy*dy + dz*dz + dw*dw) * (1.0f / 128.0f);
    float rs = rsqrtf(var + 1e-5f);
    float4 g4 = ((const float4*)gamma)[lane], e4 = ((const float4*)beta)[lane];
    float4 o = {dx*rs*g4.x + e4.x, dy*rs*g4.y + e4.y,
                dz*rs*g4.z + e4.z, dw*rs*g4.w + e4.w};
    ((float4*)outp)[d*32+lane] = o;
}

// 10) gate = sigmoid([feat|stru] @ W_gate + b_gate), FFMA2 inner loop
__global__ void __launch_bounds__(256) kgemm_gate(const float* __restrict__ Wg,
                                                  const float* __restrict__ bg) {
    __shared__ __align__(16) float As[32 * 68];
    __shared__ __align__(16) float Bs[32 * 132];
    int t = threadIdx.x, tx = t & 15, ty = t >> 4;
    int rowbase = blockIdx.x * 64;
    ull acc2[4][4];
#pragma unroll
    for (int ri = 0; ri < 4; ri++)
#pragma unroll
        for (int cj = 0; cj < 4; cj++) acc2[ri][cj] = 0ull;

    for (int kc = 0; kc < 8; kc++) {
        const float* Asrc = (kc < 4) ? d_feat : d_stru;
        int kcol = (kc & 3) * 32;
        __syncthreads();
#pragma unroll
        for (int j = 0; j < 2; j++) {
            int idx = t + j * 256;
            int r = idx >> 3, k4 = idx & 7;
            float4 v = *(const float4*)&Asrc[(rowbase + r) * FDIM + kcol + k4 * 4];
            As[(k4 * 4 + 0) * 68 + r] = v.x; As[(k4 * 4 + 1) * 68 + r] = v.y;
            As[(k4 * 4 + 2) * 68 + r] = v.z; As[(k4 * 4 + 3) * 68 + r] = v.w;
        }
#pragma unroll
        for (int j = 0; j < 4; j++) {
            int idx = t + j * 256;
            int kk = idx >> 5, c4 = idx & 31;
            *(float4*)&Bs[kk * 132 + c4 * 4] = *(const float4*)&Wg[(kc * 32 + kk) * FDIM + c4 * 4];
        }
        __syncthreads();
#pragma unroll 8
        for (int k = 0; k < 32; k++) {
            float4 a = *(const float4*)&As[k * 68 + ty * 4];
            ulonglong2 bb0 = *(const ulonglong2*)&Bs[k * 132 + tx * 4];
            ulonglong2 bb1 = *(const ulonglong2*)&Bs[k * 132 + 64 + tx * 4];
            ull ap[4] = {dup2(a.x), dup2(a.y), dup2(a.z), dup2(a.w)};
#pragma unroll
            for (int ri = 0; ri < 4; ri++) {
                ffma2(acc2[ri][0], ap[ri], bb0.x);
                ffma2(acc2[ri][1], ap[ri], bb0.y);
                ffma2(acc2[ri][2], ap[ri], bb1.x);
                ffma2(acc2[ri][3], ap[ri], bb1.y);
            }
        }
    }
#pragma unroll
    for (int ri = 0; ri < 4; ri++) {
        int row = rowbase + ty * 4 + ri;
#pragma unroll
        for (int cj = 0; cj < 4; cj++) {
            float2 p = unpack2(acc2[ri][cj]);
            int col0 = (cj < 2) ? (tx * 4 + cj * 2) : (64 + tx * 4 + (cj - 2) * 2);
            float z0 = p.x + bg[col0];
            float z1 = p.y + bg[col0 + 1];
            d_gate[row * FDIM + col0]     = 1.0f / (1.0f + expf(-z0));
            d_gate[row * FDIM + col0 + 1] = 1.0f / (1.0f + expf(-z1));
        }
    }
}

// 11) fuse + layernorm + residual
__global__ void kfinal(const float* __restrict__ x, const float* __restrict__ gamma,
                       const float* __restrict__ beta, float* __restrict__ out) {
    int d = (blockIdx.x * blockDim.x + threadIdx.x) >> 5;
    int lane = threadIdx.x & 31;
    float4 f = ((const float4*)d_feat)[d*32+lane];
    float4 s = ((const float4*)d_stru)[d*32+lane];
    float4 g = ((const float4*)d_gate)[d*32+lane];
    float4 xv = ((const float4*)x)[d*32+lane];
    float fx = g.x*f.x + (1.f-g.x)*s.x;
    float fy = g.y*f.y + (1.f-g.y)*s.y;
    float fz = g.z*f.z + (1.f-g.z)*s.z;
    float fw = g.w*f.w + (1.f-g.w)*s.w;
    float mean = warp_sum(fx + fy + fz + fw) * (1.0f / 128.0f);
    float dx = fx-mean, dy = fy-mean, dz = fz-mean, dw = fw-mean;
    float var = warp_sum(dx*dx + dy*dy + dz*dz + dw*dw) * (1.0f / 128.0f);
    float rs = rsqrtf(var + 1e-5f);
    float4 g4 = ((const float4*)gamma)[lane], b4 = ((const float4*)beta)[lane];
    float4 o = {dx*rs*g4.x + b4.x + xv.x, dy*rs*g4.y + b4.y + xv.y,
                dz*rs*g4.z + b4.z + xv.z, dw*rs*g4.w + b4.w + xv.w};
    ((float4*)out)[d*32+lane] = o;
}

extern "C" void kernel_launch(void* const* d_in, const int* in_sizes, int n_in,
                              void* d_out, int out_size) {
    const float* x      = (const float*)d_in[0];
    const int*   ei     = (const int*)  d_in[1];
    const float* W_feat = (const float*)d_in[2];
    const float* b_feat = (const float*)d_in[3];
    const float* W_stru = (const float*)d_in[4];
    const float* b_stru = (const float*)d_in[5];
    const float* W_gate = (const float*)d_in[6];
    const float* b_gate = (const float*)d_in[7];
    const float* g_feat = (const float*)d_in[8];
    const float* be_feat= (const float*)d_in[9];
    const float* g_stru = (const float*)d_in[10];
    const float* be_stru= (const float*)d_in[11];
    const float* g_fus  = (const float*)d_in[12];
    const float* be_fus = (const float*)d_in[13];
    float* out = (float*)d_out;

    knorm<<<NUM, 128>>>(x);
    kinit<<<NUM / 256, 256>>>();
    kcnt_s<<<NE / 256, 256>>>(ei);
    ktopk<<<dim3(16, 64), 256>>>();
    kgemm_h<<<dim3(NUM / 64, 1, 2), 256>>>(x, W_feat, W_stru);
    kscan<<<2, 1024>>>();
    kdinv<<<NUM / 256, 256>>>();
    kfill_f<<<(NUM * KSEL) / 256, 256>>>();
    kfill_s<<<NE / 256, 256>>>(ei);
    kagg<<<(NUM * 32) / 256, 256>>>(0, b_feat, g_feat, be_feat);
    kagg<<<(NUM * 32) / 256, 256>>>(1, b_stru, g_stru, be_stru);
    kgemm_gate<<<NUM / 64, 256>>>(W_gate, b_gate);
    kfinal<<<(NUM * 32) / 256, 256>>>(x, g_fus, be_fus, out);
}

// round 12
// speedup vs baseline: 1.2460x; 1.2460x over previous
#include <cuda_runtime.h>
#include <cuda_bf16.h>
#include <mma.h>
#include <math.h>

using namespace nvcuda;

#define BGRAPH 64
#define NNODE  1024
#define FDIM   128
#define NUM    (BGRAPH*NNODE)
#define NE     2097152
#define KSEL   4

__device__ float d_xn  [NUM*FDIM];
__device__ float d_hf  [NUM*FDIM];
__device__ float d_hs  [NUM*FDIM];
__device__ float d_feat[NUM*FDIM];
__device__ float d_stru[NUM*FDIM];
__device__ float d_gate[NUM*FDIM];
__device__ int   d_topk[NUM*KSEL];
__device__ int   d_cand[NUM*8];
__device__ int   d_cntf[NUM];
__device__ int   d_cnts[NUM];
__device__ int   d_offf[NUM];
__device__ int   d_offs[NUM];
__device__ int   d_fillf[NUM];
__device__ int   d_fills[NUM];
__device__ float d_dinvf[NUM];
__device__ float d_dinvs[NUM];
__device__ int   d_csrf[NUM*KSEL];
__device__ int   d_csrs[NE];
__device__ __align__(16) __nv_bfloat16 d_xa[NUM*FDIM];
__device__ __align__(16) __nv_bfloat16 d_xb[NUM*FDIM];

typedef unsigned long long ull;

__device__ __forceinline__ float warp_sum(float v) {
#pragma unroll
    for (int o = 16; o > 0; o >>= 1) v += __shfl_xor_sync(0xffffffffu, v, o);
    return v;
}

__device__ __forceinline__ void ins4(ull& k0, ull& k1, ull& k2, ull& k3, ull c) {
    if (c < k3) {
        k3 = c;
        if (k3 < k2) { ull t = k2; k2 = k3; k3 = t; }
        if (k2 < k1) { ull t = k1; k1 = k2; k2 = t; }
        if (k1 < k0) { ull t = k0; k0 = k1; k1 = t; }
    }
}

// 1) row-normalize x
__global__ void knorm(const float* __restrict__ x) {
    int row = blockIdx.x, t = threadIdx.x;
    float v = x[row * FDIM + t];
    float ss = warp_sum(v * v);
    __shared__ float sh[4];
    if ((t & 31) == 0) sh[t >> 5] = ss;
    __syncthreads();
    float tot = sh[0] + sh[1] + sh[2] + sh[3];
    float den = fmaxf(sqrtf(tot), 1e-8f);
    d_xn[row * FDIM + t] = v / den;
}

// 1b) split xn into two bf16 planes, plain row-major
__global__ void ksplit() {
    int i = blockIdx.x * 256 + threadIdx.x;
    float x = d_xn[i];
    __nv_bfloat16 a = __float2bfloat16(x);
    float r = x - __bfloat162float(a);
    d_xa[i] = a;
    d_xb[i] = __float2bfloat16(r);
}

// 2) zero counters
__global__ void kinit() {
    int i = blockIdx.x * blockDim.x + threadIdx.x;
    if (i < NUM) { d_cntf[i] = 0; d_cnts[i] = 0; d_fillf[i] = 0; d_fills[i] = 0; }
}

// 3) structural in-degree
__global__ void kcnt_s(const int* __restrict__ ei) {
    int e = blockIdx.x * blockDim.x + threadIdx.x;
    if (e < NE) atomicAdd(&d_cnts[ei[NE + e]], 1);
}

// 4a) candidate generation: WMMA bf16 2-plane approx distances, 8 candidates/row.
// grid(8, 64), 256 threads. Warp w owns rows rcbase + 16w .. +15.
__global__ void __launch_bounds__(256) ktopk_wmma() {
    __shared__ __align__(16) __nv_bfloat16 Bs[128 * 128];
    __shared__ __align__(16) float scr[8][16 * 20];
    const int g = blockIdx.y;
    const int rcbase = blockIdx.x * 128;
    const int tid = threadIdx.x, w = tid >> 5, lane = tid & 31;
    const int rowstart = rcbase + w * 16;
    const __nv_bfloat16* xa = d_xa + (size_t)g * NNODE * FDIM;
    const __nv_bfloat16* xb = d_xb + (size_t)g * NNODE * FDIM;

    wmma::fragment<wmma::matrix_a, 16, 16, 16, __nv_bfloat16, wmma::row_major> a0[8], a1[8];
#pragma unroll
    for (int kt = 0; kt < 8; kt++) {
        wmma::load_matrix_sync(a0[kt], xa + (size_t)rowstart * FDIM + kt * 16, FDIM);
        wmma::load_matrix_sync(a1[kt], xb + (size_t)rowstart * FDIM + kt * 16, FDIM);
    }

    ull tk0 = ~0ull, tk1 = ~0ull, tk2 = ~0ull, tk3 = ~0ull;

    for (int cc = 0; cc < 8; cc++) {
        wmma::fragment<wmma::accumulator, 16, 16, 16, float> c[8];
#pragma unroll
        for (int ct = 0; ct < 8; ct++) wmma::fill_fragment(c[ct], 0.0f);

        for (int pb = 0; pb < 2; pb++) {
            __syncthreads();
            {
                const uint4* src = (const uint4*)((pb ? xb : xa) + (size_t)cc * 128 * FDIM);
                uint4* dst = (uint4*)Bs;
                for (int i = tid; i < 2048; i += 256) dst[i] = src[i];
            }
            __syncthreads();
#pragma unroll
            for (int ct = 0; ct < 8; ct++) {
#pragma unroll
                for (int kt = 0; kt < 8; kt++) {
                    wmma::fragment<wmma::matrix_b, 16, 16, 16, __nv_bfloat16, wmma::col_major> b;
                    wmma::load_matrix_sync(b, Bs + ct * 16 * 128 + kt * 16, 128);
                    if (pb == 0) {
                        wmma::mma_sync(c[ct], a0[kt], b, c[ct]);
                        wmma::mma_sync(c[ct], a1[kt], b, c[ct]);
                    } else {
                        wmma::mma_sync(c[ct], a0[kt], b, c[ct]);
                    }
                }
            }
        }

        // extract: two lanes per row (lane r: cols lo 8, lane r+16: cols hi 8)
#pragma unroll
        for (int ct = 0; ct < 8; ct++) {
            wmma::store_matrix_sync(&scr[w][0], c[ct], 20, wmma::mem_row_major);
            __syncwarp();
            int r = lane & 15, half = lane >> 4;
            int colbase = cc * 128 + ct * 16 + half * 8;
#pragma unroll
            for (int q = 0; q < 8; q++) {
                float s = scr[w][r * 20 + half * 8 + q];
                float dval = 1.0f - s;
                unsigned u = __float_as_uint(dval);
                u = (u & 0x80000000u) ? ~u : (u | 0x80000000u);
                ull key = (((ull)(~u)) << 10) | (ull)(colbase + q);
                ins4(tk0, tk1, tk2, tk3, key);
            }
            __syncwarp();
        }
    }

    // publish 8 candidates per row: lane r -> slots 0..3, lane r+16 -> slots 4..7
    {
        int r = lane & 15, half = lane >> 4;
        int grow = g * NNODE + rowstart + r;
        ull ks[4] = {tk0, tk1, tk2, tk3};
#pragma unroll
        for (int q = 0; q < 4; q++) {
            d_cand[grow * 8 + half * 4 + q] = g * NNODE + (int)(ks[q] & 1023ull);
        }
    }
}

// 4b) exact fp32 rescore of the 8 candidates -> final top-4 (one warp per row)
__global__ void krescore() {
    int d = (blockIdx.x * blockDim.x + threadIdx.x) >> 5;
    int lane = threadIdx.x & 31;
    const float4* xn4 = (const float4*)d_xn;
    float4 xr = xn4[d * 32 + lane];
    ull k0 = ~0ull, k1 = ~0ull, k2 = ~0ull, k3 = ~0ull;
#pragma unroll
    for (int q = 0; q < 8; q++) {
        int cand = d_cand[d * 8 + q];
        float4 y = xn4[cand * 32 + lane];
        float dot = warp_sum(xr.x * y.x + xr.y * y.y + xr.z * y.z + xr.w * y.w);
        float dval = 1.0f - dot;
        unsigned u = __float_as_uint(dval);
        u = (u & 0x80000000u) ? ~u : (u | 0x80000000u);
        ull key = (((ull)(~u)) << 10) | (ull)(cand & 1023);
        ins4(k0, k1, k2, k3, key);
    }
    if (lane == 0) {
        int gbase = d & ~(NNODE - 1);
        ull ks[4] = {k0, k1, k2, k3};
#pragma unroll
        for (int q = 0; q < 4; q++) {
            int j = (int)(ks[q] & 1023ull);
            int dg = gbase + j;
            d_topk[d * 4 + q] = dg;
            atomicAdd(&d_cntf[dg], 1);
        }
    }
}

// 5) exclusive scans (block 0 = feature counts, block 1 = structural)
__global__ void kscan() {
    int which = blockIdx.x;
    const int* cnt = which ? d_cnts : d_cntf;
    int* off = which ? d_offs : d_offf;
    __shared__ int sh[1024];
    int t = threadIdx.x;
    int base = t * 64;
    int sum = 0;
    for (int i = 0; i < 64; i++) sum += cnt[base + i];
    sh[t] = sum;
    __syncthreads();
    for (int o = 1; o < 1024; o <<= 1) {
        int v = (t >= o) ? sh[t - o] : 0;
        __syncthreads();
        sh[t] += v;
        __syncthreads();
    }
    int run = sh[t] - sum;
    for (int i = 0; i < 64; i++) { int c = cnt[base + i]; off[base + i] = run; run += c; }
}

// 6) dinv = rsqrt(deg) incl. self-loop
__global__ void kdinv() {
    int i = blockIdx.x * blockDim.x + threadIdx.x;
    if (i < NUM) {
        d_dinvf[i] = rsqrtf((float)(d_cntf[i] + 1));
        d_dinvs[i] = rsqrtf((float)(d_cnts[i] + 1));
    }
}

// 7) CSR fill
__global__ void kfill_f() {
    int e = blockIdx.x * blockDim.x + threadIdx.x;
    if (e < NUM * KSEL) {
        int srcn = e >> 2;
        int dg = d_topk[e];
        int pos = d_offf[dg] + atomicAdd(&d_fillf[dg], 1);
        d_csrf[pos] = srcn;
    }
}
__global__ void kfill_s(const int* __restrict__ ei) {
    int e = blockIdx.x * blockDim.x + threadIdx.x;
    if (e < NE) {
        int s = ei[e], dg = ei[NE + e];
        int pos = d_offs[dg] + atomicAdd(&d_fills[dg], 1);
        d_csrs[pos] = s;
    }
}

// 8) h = x @ W (z: 0=feat, 1=stru)
__global__ void __launch_bounds__(256) kgemm_h(const float* __restrict__ x,
                                               const float* __restrict__ Wf,
                                               const float* __restrict__ Wst) {
    const float* W = blockIdx.z ? Wst : Wf;
    float* out = blockIdx.z ? d_hs : d_hf;
    __shared__ __align__(16) float As[32 * 68];
    __shared__ __align__(16) float Bs[32 * 132];
    int t = threadIdx.x, tx = t & 15, ty = t >> 4;
    int rowbase = blockIdx.x * 64;
    float acc[4][8];
#pragma unroll
    for (int ri = 0; ri < 4; ri++)
#pragma unroll
        for (int ci = 0; ci < 8; ci++) acc[ri][ci] = 0.f;

    for (int kc = 0; kc < 4; kc++) {
        __syncthreads();
#pragma unroll
        for (int j = 0; j < 2; j++) {
            int idx = t + j * 256;
            int r = idx >> 3, k4 = idx & 7;
            float4 v = *(const float4*)&x[(rowbase + r) * FDIM + kc * 32 + k4 * 4];
            As[(k4 * 4 + 0) * 68 + r] = v.x; As[(k4 * 4 + 1) * 68 + r] = v.y;
            As[(k4 * 4 + 2) * 68 + r] = v.z; As[(k4 * 4 + 3) * 68 + r] = v.w;
        }
#pragma unroll
        for (int j = 0; j < 4; j++) {
            int idx = t + j * 256;
            int kk = idx >> 5, c4 = idx & 31;
            *(float4*)&Bs[kk * 132 + c4 * 4] = *(const float4*)&W[(kc * 32 + kk) * FDIM + c4 * 4];
        }
        __syncthreads();
#pragma unroll 8
        for (int k = 0; k < 32; k++) {
            float4 a  = *(const float4*)&As[k * 68 + ty * 4];
            float4 b0 = *(const float4*)&Bs[k * 132 + tx * 4];
            float4 b1 = *(const float4*)&Bs[k * 132 + 64 + tx * 4];
            float av[4] = {a.x, a.y, a.z, a.w};
            float bv[8] = {b0.x, b0.y, b0.z, b0.w, b1.x, b1.y, b1.z, b1.w};
#pragma unroll
            for (int ri = 0; ri < 4; ri++)
#pragma unroll
                for (int ci = 0; ci < 8; ci++) acc[ri][ci] += av[ri] * bv[ci];
        }
    }
#pragma unroll
    for (int ri = 0; ri < 4; ri++) {
        int row = rowbase + ty * 4 + ri;
        float4 o0 = {acc[ri][0], acc[ri][1], acc[ri][2], acc[ri][3]};
        float4 o1 = {acc[ri][4], acc[ri][5], acc[ri][6], acc[ri][7]};
        *(float4*)&out[row * FDIM + tx * 4] = o0;
        *(float4*)&out[row * FDIM + 64 + tx * 4] = o1;
    }
}

// 9) GCN aggregate + bias + relu + layernorm (one warp per node)
__global__ void kagg(int which, const float* __restrict__ bias,
                     const float* __restrict__ gamma, const float* __restrict__ beta) {
    int d = (blockIdx.x * blockDim.x + threadIdx.x) >> 5;
    int lane = threadIdx.x & 31;
    const int* off = which ? d_offs : d_offf;
    const int* cnt = which ? d_cnts : d_cntf;
    const int* csr = which ? d_csrs : d_csrf;
    const float* dinv = which ? d_dinvs : d_dinvf;
    const float4* h4 = which ? (const float4*)d_hs : (const float4*)d_hf;
    float* outp = which ? d_stru : d_feat;

    int st = off[d], n = cnt[d];
    float dd = dinv[d];
    float ax = 0.f, ay = 0.f, az = 0.f, aw = 0.f;
    int e = 0;
    for (; e + 4 <= n; e += 4) {
        int s0 = csr[st+e], s1 = csr[st+e+1], s2 = csr[st+e+2], s3 = csr[st+e+3];
        float w0 = dinv[s0]*dd, w1 = dinv[s1]*dd, w2 = dinv[s2]*dd, w3 = dinv[s3]*dd;
        float4 v0 = h4[s0*32+lane], v1 = h4[s1*32+lane];
        float4 v2 = h4[s2*32+lane], v3 = h4[s3*32+lane];
        ax += v0.x*w0 + v1.x*w1 + v2.x*w2 + v3.x*w3;
        ay += v0.y*w0 + v1.y*w1 + v2.y*w2 + v3.y*w3;
        az += v0.z*w0 + v1.z*w1 + v2.z*w2 + v3.z*w3;
        aw += v0.w*w0 + v1.w*w1 + v2.w*w2 + v3.w*w3;
    }
    for (; e < n; e++) {
        int s = csr[st + e];
        float wg = dinv[s] * dd;
        float4 v = h4[s*32+lane];
        ax += v.x*wg; ay += v.y*wg; az += v.z*wg; aw += v.w*wg;
    }
    {
        float4 v = h4[d*32+lane];
        float wg = dd * dd;
        ax += v.x*wg; ay += v.y*wg; az += v.z*wg; aw += v.w*wg;
    }
    float4 b4 = ((const float4*)bias)[lane];
    ax = fmaxf(ax + b4.x, 0.f); ay = fmaxf(ay + b4.y, 0.f);
    az = fmaxf(az + b4.z, 0.f); aw = fmaxf(aw + b4.w, 0.f);
    float mean = warp_sum(ax + ay + az + aw) * (1.0f / 128.0f);
    float dx = ax - mean, dy = ay - mean, dz = az - mean, dw = aw - mean;
    float var = warp_sum(dx*dx + dy*dy + dz*dz + dw*dw) * (1.0f / 128.0f);
    float rs = rsqrtf(var + 1e-5f);
    float4 g4 = ((const float4*)gamma)[lane], e4 = ((const float4*)beta)[lane];
    float4 o = {dx*rs*g4.x + e4.x, dy*rs*g4.y + e4.y,
                dz*rs*g4.z + e4.z, dw*rs*g4.w + e4.w};
    ((float4*)outp)[d*32+lane] = o;
}

// 10) gate = sigmoid([feat|stru] @ W_gate + b_gate)
__global__ void __launch_bounds__(256) kgemm_gate(const float* __restrict__ Wg,
                                                  const float* __restrict__ bg) {
    __shared__ __align__(16) float As[32 * 68];
    __shared__ __align__(16) float Bs[32 * 132];
    int t = threadIdx.x, tx = t & 15, ty = t >> 4;
    int rowbase = blockIdx.x * 64;
    float acc[4][8];
#pragma unroll
    for (int ri = 0; ri < 4; ri++)
#pragma unroll
        for (int ci = 0; ci < 8; ci++) acc[ri][ci] = 0.f;

    for (int kc = 0; kc < 8; kc++) {
        const float* Asrc = (kc < 4) ? d_feat : d_stru;
        int kcol = (kc & 3) * 32;
        __syncthreads();
#pragma unroll
        for (int j = 0; j < 2; j++) {
            int idx = t + j * 256;
            int r = idx >> 3, k4 = idx & 7;
            float4 v = *(const float4*)&Asrc[(rowbase + r) * FDIM + kcol + k4 * 4];
            As[(k4 * 4 + 0) * 68 + r] = v.x; As[(k4 * 4 + 1) * 68 + r] = v.y;
            As[(k4 * 4 + 2) * 68 + r] = v.z; As[(k4 * 4 + 3) * 68 + r] = v.w;
        }
#pragma unroll
        for (int j = 0; j < 4; j++) {
            int idx = t + j * 256;
            int kk = idx >> 5, c4 = idx & 31;
            *(float4*)&Bs[kk * 132 + c4 * 4] = *(const float4*)&Wg[(kc * 32 + kk) * FDIM + c4 * 4];
        }
        __syncthreads();
#pragma unroll 8
        for (int k = 0; k < 32; k++) {
            float4 a  = *(const float4*)&As[k * 68 + ty * 4];
            float4 b0 = *(const float4*)&Bs[k * 132 + tx * 4];
            float4 b1 = *(const float4*)&Bs[k * 132 + 64 + tx * 4];
            float av[4] = {a.x, a.y, a.z, a.w};
            float bv[8] = {b0.x, b0.y, b0.z, b0.w, b1.x, b1.y, b1.z, b1.w};
#pragma unroll
            for (int ri = 0; ri < 4; ri++)
#pragma unroll
                for (int ci = 0; ci < 8; ci++) acc[ri][ci] += av[ri] * bv[ci];
        }
    }
    float bgv[8];
#pragma unroll
    for (int ci = 0; ci < 8; ci++)
        bgv[ci] = bg[(ci < 4) ? (tx * 4 + ci) : (64 + tx * 4 + ci - 4)];
#pragma unroll
    for (int ri = 0; ri < 4; ri++) {
        int row = rowbase + ty * 4 + ri;
#pragma unroll
        for (int ci = 0; ci < 8; ci++) {
            int col = (ci < 4) ? (tx * 4 + ci) : (64 + tx * 4 + ci - 4);
            float z = acc[ri][ci] + bgv[ci];
            d_gate[row * FDIM + col] = 1.0f / (1.0f + expf(-z));
        }
    }
}

// 11) fuse + layernorm + residual
__global__ void kfinal(const float* __restrict__ x, const float* __restrict__ gamma,
                       const float* __restrict__ beta, float* __restrict__ out) {
    int d = (blockIdx.x * blockDim.x + threadIdx.x) >> 5;
    int lane = threadIdx.x & 31;
    float4 f = ((const float4*)d_feat)[d*32+lane];
    float4 s = ((const float4*)d_stru)[d*32+lane];
    float4 g = ((const float4*)d_gate)[d*32+lane];
    float4 xv = ((const float4*)x)[d*32+lane];
    float fx = g.x*f.x + (1.f-g.x)*s.x;
    float fy = g.y*f.y + (1.f-g.y)*s.y;
    float fz = g.z*f.z + (1.f-g.z)*s.z;
    float fw = g.w*f.w + (1.f-g.w)*s.w;
    float mean = warp_sum(fx + fy + fz + fw) * (1.0f / 128.0f);
    float dx = fx-mean, dy = fy-mean, dz = fz-mean, dw = fw-mean;
    float var = warp_sum(dx*dx + dy*dy + dz*dz + dw*dw) * (1.0f / 128.0f);
    float rs = rsqrtf(var + 1e-5f);
    float4 g4 = ((const float4*)gamma)[lane], b4 = ((const float4*)beta)[lane];
    float4 o = {dx*rs*g4.x + b4.x + xv.x, dy*rs*g4.y + b4.y + xv.y,
                dz*rs*g4.z + b4.z + xv.z, dw*rs*g4.w + b4.w + xv.w};
    ((float4*)out)[d*32+lane] = o;
}

extern "C" void kernel_launch(void* const* d_in, const int* in_sizes, int n_in,
                              void* d_out, int out_size) {
    const float* x      = (const float*)d_in[0];
    const int*   ei     = (const int*)  d_in[1];
    const float* W_feat = (const float*)d_in[2];
    const float* b_feat = (const float*)d_in[3];
    const float* W_stru = (const float*)d_in[4];
    const float* b_stru = (const float*)d_in[5];
    const float* W_gate = (const float*)d_in[6];
    const float* b_gate = (const float*)d_in[7];
    const float* g_feat = (const float*)d_in[8];
    const float* be_feat= (const float*)d_in[9];
    const float* g_stru = (const float*)d_in[10];
    const float* be_stru= (const float*)d_in[11];
    const float* g_fus  = (const float*)d_in[12];
    const float* be_fus = (const float*)d_in[13];
    float* out = (float*)d_out;

    knorm<<<NUM, 128>>>(x);
    kinit<<<NUM / 256, 256>>>();
    kcnt_s<<<NE / 256, 256>>>(ei);
    ksplit<<<(NUM * FDIM) / 256, 256>>>();
    ktopk_wmma<<<dim3(8, 64), 256>>>();
    krescore<<<(NUM * 32) / 256, 256>>>();
    kgemm_h<<<dim3(NUM / 64, 1, 2), 256>>>(x, W_feat, W_stru);
    kscan<<<2, 1024>>>();
    kdinv<<<NUM / 256, 256>>>();
    kfill_f<<<(NUM * KSEL) / 256, 256>>>();
    kfill_s<<<NE / 256, 256>>>(ei);
    kagg<<<(NUM * 32) / 256, 256>>>(0, b_feat, g_feat, be_feat);
    kagg<<<(NUM * 32) / 256, 256>>>(1, b_stru, g_stru, be_stru);
    kgemm_gate<<<NUM / 64, 256>>>(W_gate, b_gate);
    kfinal<<<(NUM * 32) / 256, 256>>>(x, g_fus, be_fus, out);
}

// round 13
// speedup vs baseline: 1.6653x; 1.3365x over previous
#include <cuda_runtime.h>
#include <cuda_bf16.h>
#include <mma.h>
#include <math.h>

using namespace nvcuda;

#define BGRAPH 64
#define NNODE  1024
#define FDIM   128
#define NUM    (BGRAPH*NNODE)
#define NE     2097152
#define KSEL   4
#define BLDM   136   /* padded B leading dim: 272B stride, 16B-aligned, ~conflict-free */

__device__ float d_xn  [NUM*FDIM];
__device__ float d_hf  [NUM*FDIM];
__device__ float d_hs  [NUM*FDIM];
__device__ float d_feat[NUM*FDIM];
__device__ float d_stru[NUM*FDIM];
__device__ float d_gate[NUM*FDIM];
__device__ int   d_topk[NUM*KSEL];
__device__ int   d_cand[NUM*8];
__device__ int   d_cntf[NUM];
__device__ int   d_cnts[NUM];
__device__ int   d_offf[NUM];
__device__ int   d_offs[NUM];
__device__ int   d_fillf[NUM];
__device__ int   d_fills[NUM];
__device__ float d_dinvf[NUM];
__device__ float d_dinvs[NUM];
__device__ int   d_csrf[NUM*KSEL];
__device__ int   d_csrs[NE];
__device__ __align__(16) __nv_bfloat16 d_xa[NUM*FDIM];
__device__ __align__(16) __nv_bfloat16 d_xb[NUM*FDIM];

typedef unsigned long long ull;

__device__ __forceinline__ float warp_sum(float v) {
#pragma unroll
    for (int o = 16; o > 0; o >>= 1) v += __shfl_xor_sync(0xffffffffu, v, o);
    return v;
}

__device__ __forceinline__ void ins4(ull& k0, ull& k1, ull& k2, ull& k3, ull c) {
    if (c < k3) {
        k3 = c;
        if (k3 < k2) { ull t = k2; k2 = k3; k3 = t; }
        if (k2 < k1) { ull t = k1; k1 = k2; k2 = t; }
        if (k1 < k0) { ull t = k0; k0 = k1; k1 = t; }
    }
}

// 1) row-normalize x + emit 2-plane bf16 split (fused)
__global__ void knorm(const float* __restrict__ x) {
    int row = blockIdx.x, t = threadIdx.x;
    float v = x[row * FDIM + t];
    float ss = warp_sum(v * v);
    __shared__ float sh[4];
    if ((t & 31) == 0) sh[t >> 5] = ss;
    __syncthreads();
    float tot = sh[0] + sh[1] + sh[2] + sh[3];
    float den = fmaxf(sqrtf(tot), 1e-8f);
    float xv = v / den;
    int i = row * FDIM + t;
    d_xn[i] = xv;
    __nv_bfloat16 a = __float2bfloat16(xv);
    d_xa[i] = a;
    d_xb[i] = __float2bfloat16(xv - __bfloat162float(a));
}

// 2) zero counters
__global__ void kinit() {
    int i = blockIdx.x * blockDim.x + threadIdx.x;
    if (i < NUM) { d_cntf[i] = 0; d_cnts[i] = 0; d_fillf[i] = 0; d_fills[i] = 0; }
}

// 3) structural in-degree
__global__ void kcnt_s(const int* __restrict__ ei) {
    int e = blockIdx.x * blockDim.x + threadIdx.x;
    if (e < NE) atomicAdd(&d_cnts[ei[NE + e]], 1);
}

// 4a) candidate generation: WMMA bf16 2-plane approx distances, 8 candidates/row.
// grid(8, 64), 256 threads. Warp w owns rows rcbase + 16w .. +15.
__global__ void __launch_bounds__(256) ktopk_wmma() {
    __shared__ __align__(16) __nv_bfloat16 Bs[128 * BLDM];
    __shared__ __align__(16) float scr[8][16 * 20];
    const int g = blockIdx.y;
    const int rcbase = blockIdx.x * 128;
    const int tid = threadIdx.x, w = tid >> 5, lane = tid & 31;
    const int rowstart = rcbase + w * 16;
    const __nv_bfloat16* xa = d_xa + (size_t)g * NNODE * FDIM;
    const __nv_bfloat16* xb = d_xb + (size_t)g * NNODE * FDIM;

    wmma::fragment<wmma::matrix_a, 16, 16, 16, __nv_bfloat16, wmma::row_major> a0[8], a1[8];
#pragma unroll
    for (int kt = 0; kt < 8; kt++) {
        wmma::load_matrix_sync(a0[kt], xa + (size_t)rowstart * FDIM + kt * 16, FDIM);
        wmma::load_matrix_sync(a1[kt], xb + (size_t)rowstart * FDIM + kt * 16, FDIM);
    }

    ull tk0 = ~0ull, tk1 = ~0ull, tk2 = ~0ull, tk3 = ~0ull;

    for (int cc = 0; cc < 8; cc++) {
        wmma::fragment<wmma::accumulator, 16, 16, 16, float> c[8];
#pragma unroll
        for (int ct = 0; ct < 8; ct++) wmma::fill_fragment(c[ct], 0.0f);

        for (int pb = 0; pb < 2; pb++) {
            __syncthreads();
            {
                // stage 128 cols x 128 k with padded ldm: dst uint4 index = col*17 + kk
                const uint4* src = (const uint4*)((pb ? xb : xa) + (size_t)cc * 128 * FDIM);
                uint4* dst = (uint4*)Bs;
                for (int i = tid; i < 2048; i += 256) {
                    int col = i >> 4, kk = i & 15;
                    dst[col * 17 + kk] = src[i];
                }
            }
            __syncthreads();
#pragma unroll
            for (int ct = 0; ct < 8; ct++) {
#pragma unroll
                for (int kt = 0; kt < 8; kt++) {
                    wmma::fragment<wmma::matrix_b, 16, 16, 16, __nv_bfloat16, wmma::col_major> b;
                    wmma::load_matrix_sync(b, Bs + ct * 16 * BLDM + kt * 16, BLDM);
                    if (pb == 0) {
                        wmma::mma_sync(c[ct], a0[kt], b, c[ct]);
                        wmma::mma_sync(c[ct], a1[kt], b, c[ct]);
                    } else {
                        wmma::mma_sync(c[ct], a0[kt], b, c[ct]);
                    }
                }
            }
        }

        // extract: two lanes per row (lane r: cols lo 8, lane r+16: cols hi 8)
#pragma unroll
        for (int ct = 0; ct < 8; ct++) {
            wmma::store_matrix_sync(&scr[w][0], c[ct], 20, wmma::mem_row_major);
            __syncwarp();
            int r = lane & 15, half = lane >> 4;
            int colbase = cc * 128 + ct * 16 + half * 8;
#pragma unroll
            for (int q = 0; q < 8; q++) {
                float s = scr[w][r * 20 + half * 8 + q];
                float dval = 1.0f - s;
                unsigned u = __float_as_uint(dval);
                u = (u & 0x80000000u) ? ~u : (u | 0x80000000u);
                ull key = (((ull)(~u)) << 10) | (ull)(colbase + q);
                ins4(tk0, tk1, tk2, tk3, key);
            }
            __syncwarp();
        }
    }

    // publish 8 candidates per row: lane r -> slots 0..3, lane r+16 -> slots 4..7
    {
        int r = lane & 15, half = lane >> 4;
        int grow = g * NNODE + rowstart + r;
        ull ks[4] = {tk0, tk1, tk2, tk3};
#pragma unroll
        for (int q = 0; q < 4; q++) {
            d_cand[grow * 8 + half * 4 + q] = g * NNODE + (int)(ks[q] & 1023ull);
        }
    }
}

// 4b) exact fp32 rescore of the 8 candidates -> final top-4 (one warp per row)
__global__ void krescore() {
    int d = (blockIdx.x * blockDim.x + threadIdx.x) >> 5;
    int lane = threadIdx.x & 31;
    const float4* xn4 = (const float4*)d_xn;
    float4 xr = xn4[d * 32 + lane];
    ull k0 = ~0ull, k1 = ~0ull, k2 = ~0ull, k3 = ~0ull;
#pragma unroll
    for (int q = 0; q < 8; q++) {
        int cand = d_cand[d * 8 + q];
        float4 y = xn4[cand * 32 + lane];
        float dot = warp_sum(xr.x * y.x + xr.y * y.y + xr.z * y.z + xr.w * y.w);
        float dval = 1.0f - dot;
        unsigned u = __float_as_uint(dval);
        u = (u & 0x80000000u) ? ~u : (u | 0x80000000u);
        ull key = (((ull)(~u)) << 10) | (ull)(cand & 1023);
        ins4(k0, k1, k2, k3, key);
    }
    if (lane == 0) {
        int gbase = d & ~(NNODE - 1);
        ull ks[4] = {k0, k1, k2, k3};
#pragma unroll
        for (int q = 0; q < 4; q++) {
            int j = (int)(ks[q] & 1023ull);
            int dg = gbase + j;
            d_topk[d * 4 + q] = dg;
            atomicAdd(&d_cntf[dg], 1);
        }
    }
}

// 5) exclusive scans (block 0 = feature counts, block 1 = structural)
__global__ void kscan() {
    int which = blockIdx.x;
    const int* cnt = which ? d_cnts : d_cntf;
    int* off = which ? d_offs : d_offf;
    __shared__ int sh[1024];
    int t = threadIdx.x;
    int base = t * 64;
    int sum = 0;
    for (int i = 0; i < 64; i++) sum += cnt[base + i];
    sh[t] = sum;
    __syncthreads();
    for (int o = 1; o < 1024; o <<= 1) {
        int v = (t >= o) ? sh[t - o] : 0;
        __syncthreads();
        sh[t] += v;
        __syncthreads();
    }
    int run = sh[t] - sum;
    for (int i = 0; i < 64; i++) { int c = cnt[base + i]; off[base + i] = run; run += c; }
}

// 6) dinv = rsqrt(deg) incl. self-loop
__global__ void kdinv() {
    int i = blockIdx.x * blockDim.x + threadIdx.x;
    if (i < NUM) {
        d_dinvf[i] = rsqrtf((float)(d_cntf[i] + 1));
        d_dinvs[i] = rsqrtf((float)(d_cnts[i] + 1));
    }
}

// 7) CSR fill
__global__ void kfill_f() {
    int e = blockIdx.x * blockDim.x + threadIdx.x;
    if (e < NUM * KSEL) {
        int srcn = e >> 2;
        int dg = d_topk[e];
        int pos = d_offf[dg] + atomicAdd(&d_fillf[dg], 1);
        d_csrf[pos] = srcn;
    }
}
__global__ void kfill_s(const int* __restrict__ ei) {
    int e = blockIdx.x * blockDim.x + threadIdx.x;
    if (e < NE) {
        int s = ei[e], dg = ei[NE + e];
        int pos = d_offs[dg] + atomicAdd(&d_fills[dg], 1);
        d_csrs[pos] = s;
    }
}

// 8) h = x @ W (z: 0=feat, 1=stru)
__global__ void __launch_bounds__(256) kgemm_h(const float* __restrict__ x,
                                               const float* __restrict__ Wf,
                                               const float* __restrict__ Wst) {
    const float* W = blockIdx.z ? Wst : Wf;
    float* out = blockIdx.z ? d_hs : d_hf;
    __shared__ __align__(16) float As[32 * 68];
    __shared__ __align__(16) float Bs[32 * 132];
    int t = threadIdx.x, tx = t & 15, ty = t >> 4;
    int rowbase = blockIdx.x * 64;
    float acc[4][8];
#pragma unroll
    for (int ri = 0; ri < 4; ri++)
#pragma unroll
        for (int ci = 0; ci < 8; ci++) acc[ri][ci] = 0.f;

    for (int kc = 0; kc < 4; kc++) {
        __syncthreads();
#pragma unroll
        for (int j = 0; j < 2; j++) {
            int idx = t + j * 256;
            int r = idx >> 3, k4 = idx & 7;
            float4 v = *(const float4*)&x[(rowbase + r) * FDIM + kc * 32 + k4 * 4];
            As[(k4 * 4 + 0) * 68 + r] = v.x; As[(k4 * 4 + 1) * 68 + r] = v.y;
            As[(k4 * 4 + 2) * 68 + r] = v.z; As[(k4 * 4 + 3) * 68 + r] = v.w;
        }
#pragma unroll
        for (int j = 0; j < 4; j++) {
            int idx = t + j * 256;
            int kk = idx >> 5, c4 = idx & 31;
            *(float4*)&Bs[kk * 132 + c4 * 4] = *(const float4*)&W[(kc * 32 + kk) * FDIM + c4 * 4];
        }
        __syncthreads();
#pragma unroll 8
        for (int k = 0; k < 32; k++) {
            float4 a  = *(const float4*)&As[k * 68 + ty * 4];
            float4 b0 = *(const float4*)&Bs[k * 132 + tx * 4];
            float4 b1 = *(const float4*)&Bs[k * 132 + 64 + tx * 4];
            float av[4] = {a.x, a.y, a.z, a.w};
            float bv[8] = {b0.x, b0.y, b0.z, b0.w, b1.x, b1.y, b1.z, b1.w};
#pragma unroll
            for (int ri = 0; ri < 4; ri++)
#pragma unroll
                for (int ci = 0; ci < 8; ci++) acc[ri][ci] += av[ri] * bv[ci];
        }
    }
#pragma unroll
    for (int ri = 0; ri < 4; ri++) {
        int row = rowbase + ty * 4 + ri;
        float4 o0 = {acc[ri][0], acc[ri][1], acc[ri][2], acc[ri][3]};
        float4 o1 = {acc[ri][4], acc[ri][5], acc[ri][6], acc[ri][7]};
        *(float4*)&out[row * FDIM + tx * 4] = o0;
        *(float4*)&out[row * FDIM + 64 + tx * 4] = o1;
    }
}

// 9) GCN aggregate + bias + relu + layernorm (one warp per node)
__global__ void kagg(int which, const float* __restrict__ bias,
                     const float* __restrict__ gamma, const float* __restrict__ beta) {
    int d = (blockIdx.x * blockDim.x + threadIdx.x) >> 5;
    int lane = threadIdx.x & 31;
    const int* off = which ? d_offs : d_offf;
    const int* cnt = which ? d_cnts : d_cntf;
    const int* csr = which ? d_csrs : d_csrf;
    const float* dinv = which ? d_dinvs : d_dinvf;
    const float4* h4 = which ? (const float4*)d_hs : (const float4*)d_hf;
    float* outp = which ? d_stru : d_feat;

    int st = off[d], n = cnt[d];
    float dd = dinv[d];
    float ax = 0.f, ay = 0.f, az = 0.f, aw = 0.f;
    int e = 0;
    for (; e + 4 <= n; e += 4) {
        int s0 = csr[st+e], s1 = csr[st+e+1], s2 = csr[st+e+2], s3 = csr[st+e+3];
        float w0 = dinv[s0]*dd, w1 = dinv[s1]*dd, w2 = dinv[s2]*dd, w3 = dinv[s3]*dd;
        float4 v0 = h4[s0*32+lane], v1 = h4[s1*32+lane];
        float4 v2 = h4[s2*32+lane], v3 = h4[s3*32+lane];
        ax += v0.x*w0 + v1.x*w1 + v2.x*w2 + v3.x*w3;
        ay += v0.y*w0 + v1.y*w1 + v2.y*w2 + v3.y*w3;
        az += v0.z*w0 + v1.z*w1 + v2.z*w2 + v3.z*w3;
        aw += v0.w*w0 + v1.w*w1 + v2.w*w2 + v3.w*w3;
    }
    for (; e < n; e++) {
        int s = csr[st + e];
        float wg = dinv[s] * dd;
        float4 v = h4[s*32+lane];
        ax += v.x*wg; ay += v.y*wg; az += v.z*wg; aw += v.w*wg;
    }
    {
        float4 v = h4[d*32+lane];
        float wg = dd * dd;
        ax += v.x*wg; ay += v.y*wg; az += v.z*wg; aw += v.w*wg;
    }
    float4 b4 = ((const float4*)bias)[lane];
    ax = fmaxf(ax + b4.x, 0.f); ay = fmaxf(ay + b4.y, 0.f);
    az = fmaxf(az + b4.z, 0.f); aw = fmaxf(aw + b4.w, 0.f);
    float mean = warp_sum(ax + ay + az + aw) * (1.0f / 128.0f);
    float dx = ax - mean, dy = ay - mean, dz = az - mean, dw = aw - mean;
    float var = warp_sum(dx*dx + dy*dy + dz*dz + dw*dw) * (1.0f / 128.0f);
    float rs = rsqrtf(var + 1e-5f);
    float4 g4 = ((const float4*)gamma)[lane], e4 = ((const float4*)beta)[lane];
    float4 o = {dx*rs*g4.x + e4.x, dy*rs*g4.y + e4.y,
                dz*rs*g4.z + e4.z, dw*rs*g4.w + e4.w};
    ((float4*)outp)[d*32+lane] = o;
}

// 10) gate = sigmoid([feat|stru] @ W_gate + b_gate)
__global__ void __launch_bounds__(256) kgemm_gate(const float* __restrict__ Wg,
                                                  const float* __restrict__ bg) {
    __shared__ __align__(16) float As[32 * 68];
    __shared__ __align__(16) float Bs[32 * 132];
    int t = threadIdx.x, tx = t & 15, ty = t >> 4;
    int rowbase = blockIdx.x * 64;
    float acc[4][8];
#pragma unroll
    for (int ri = 0; ri < 4; ri++)
#pragma unroll
        for (int ci = 0; ci < 8; ci++) acc[ri][ci] = 0.f;

    for (int kc = 0; kc < 8; kc++) {
        const float* Asrc = (kc < 4) ? d_feat : d_stru;
        int kcol = (kc & 3) * 32;
        __syncthreads();
#pragma unroll
        for (int j = 0; j < 2; j++) {
            int idx = t + j * 256;
            int r = idx >> 3, k4 = idx & 7;
            float4 v = *(const float4*)&Asrc[(rowbase + r) * FDIM + kcol + k4 * 4];
            As[(k4 * 4 + 0) * 68 + r] = v.x; As[(k4 * 4 + 1) * 68 + r] = v.y;
            As[(k4 * 4 + 2) * 68 + r] = v.z; As[(k4 * 4 + 3) * 68 + r] = v.w;
        }
#pragma unroll
        for (int j = 0; j < 4; j++) {
            int idx = t + j * 256;
            int kk = idx >> 5, c4 = idx & 31;
            *(float4*)&Bs[kk * 132 + c4 * 4] = *(const float4*)&Wg[(kc * 32 + kk) * FDIM + c4 * 4];
        }
        __syncthreads();
#pragma unroll 8
        for (int k = 0; k < 32; k++) {
            float4 a  = *(const float4*)&As[k * 68 + ty * 4];
            float4 b0 = *(const float4*)&Bs[k * 132 + tx * 4];
            float4 b1 = *(const float4*)&Bs[k * 132 + 64 + tx * 4];
            float av[4] = {a.x, a.y, a.z, a.w};
            float bv[8] = {b0.x, b0.y, b0.z, b0.w, b1.x, b1.y, b1.z, b1.w};
#pragma unroll
            for (int ri = 0; ri < 4; ri++)
#pragma unroll
                for (int ci = 0; ci < 8; ci++) acc[ri][ci] += av[ri] * bv[ci];
        }
    }
    float bgv[8];
#pragma unroll
    for (int ci = 0; ci < 8; ci++)
        bgv[ci] = bg[(ci < 4) ? (tx * 4 + ci) : (64 + tx * 4 + ci - 4)];
#pragma unroll
    for (int ri = 0; ri < 4; ri++) {
        int row = rowbase + ty * 4 + ri;
#pragma unroll
        for (int ci = 0; ci < 8; ci++) {
            int col = (ci < 4) ? (tx * 4 + ci) : (64 + tx * 4 + ci - 4);
            float z = acc[ri][ci] + bgv[ci];
            d_gate[row * FDIM + col] = 1.0f / (1.0f + expf(-z));
        }
    }
}

// 11) fuse + layernorm + residual
__global__ void kfinal(const float* __restrict__ x, const float* __restrict__ gamma,
                       const float* __restrict__ beta, float* __restrict__ out) {
    int d = (blockIdx.x * blockDim.x + threadIdx.x) >> 5;
    int lane = threadIdx.x & 31;
    float4 f = ((const float4*)d_feat)[d*32+lane];
    float4 s = ((const float4*)d_stru)[d*32+lane];
    float4 g = ((const float4*)d_gate)[d*32+lane];
    float4 xv = ((const float4*)x)[d*32+lane];
    float fx = g.x*f.x + (1.f-g.x)*s.x;
    float fy = g.y*f.y + (1.f-g.y)*s.y;
    float fz = g.z*f.z + (1.f-g.z)*s.z;
    float fw = g.w*f.w + (1.f-g.w)*s.w;
    float mean = warp_sum(fx + fy + fz + fw) * (1.0f / 128.0f);
    float dx = fx-mean, dy = fy-mean, dz = fz-mean, dw = fw-mean;
    float var = warp_sum(dx*dx + dy*dy + dz*dz + dw*dw) * (1.0f / 128.0f);
    float rs = rsqrtf(var + 1e-5f);
    float4 g4 = ((const float4*)gamma)[lane], b4 = ((const float4*)beta)[lane];
    float4 o = {dx*rs*g4.x + b4.x + xv.x, dy*rs*g4.y + b4.y + xv.y,
                dz*rs*g4.z + b4.z + xv.z, dw*rs*g4.w + b4.w + xv.w};
    ((float4*)out)[d*32+lane] = o;
}

extern "C" void kernel_launch(void* const* d_in, const int* in_sizes, int n_in,
                              void* d_out, int out_size) {
    const float* x      = (const float*)d_in[0];
    const int*   ei     = (const int*)  d_in[1];
    const float* W_feat = (const float*)d_in[2];
    const float* b_feat = (const float*)d_in[3];
    const float* W_stru = (const float*)d_in[4];
    const float* b_stru = (const float*)d_in[5];
    const float* W_gate = (const float*)d_in[6];
    const float* b_gate = (const float*)d_in[7];
    const float* g_feat = (const float*)d_in[8];
    const float* be_feat= (const float*)d_in[9];
    const float* g_stru = (const float*)d_in[10];
    const float* be_stru= (const float*)d_in[11];
    const float* g_fus  = (const float*)d_in[12];
    const float* be_fus = (const float*)d_in[13];
    float* out = (float*)d_out;

    knorm<<<NUM, 128>>>(x);
    kinit<<<NUM / 256, 256>>>();
    kcnt_s<<<NE / 256, 256>>>(ei);
    ktopk_wmma<<<dim3(8, 64), 256>>>();
    krescore<<<(NUM * 32) / 256, 256>>>();
    kgemm_h<<<dim3(NUM / 64, 1, 2), 256>>>(x, W_feat, W_stru);
    kscan<<<2, 1024>>>();
    kdinv<<<NUM / 256, 256>>>();
    kfill_f<<<(NUM * KSEL) / 256, 256>>>();
    kfill_s<<<NE / 256, 256>>>(ei);
    kagg<<<(NUM * 32) / 256, 256>>>(0, b_feat, g_feat, be_feat);
    kagg<<<(NUM * 32) / 256, 256>>>(1, b_stru, g_stru, be_stru);
    kgemm_gate<<<NUM / 64, 256>>>(W_gate, b_gate);
    kfinal<<<(NUM * 32) / 256, 256>>>(x, g_fus, be_fus, out);
}

// round 14
// speedup vs baseline: 1.8775x; 1.1274x over previous
#include <cuda_runtime.h>
#include <cuda_bf16.h>
#include <mma.h>
#include <math.h>

using namespace nvcuda;

#define BGRAPH 64
#define NNODE  1024
#define FDIM   128
#define NUM    (BGRAPH*NNODE)
#define NE     2097152
#define KSEL   4
#define BLDM   136   /* padded B leading dim: 272B stride, 16B-aligned, ~conflict-free */

__device__ float d_xn  [NUM*FDIM];
__device__ float d_hf  [NUM*FDIM];
__device__ float d_hs  [NUM*FDIM];
__device__ float d_feat[NUM*FDIM];
__device__ float d_stru[NUM*FDIM];
__device__ float d_gate[NUM*FDIM];
__device__ int   d_topk[NUM*KSEL];
__device__ int   d_cand[NUM*8];
__device__ int   d_cntf[NUM];
__device__ int   d_cnts[NUM];
__device__ int   d_offf[NUM];
__device__ int   d_offs[NUM];
__device__ int   d_fillf[NUM];
__device__ int   d_fills[NUM];
__device__ float d_dinvf[NUM];
__device__ float d_dinvs[NUM];
__device__ int   d_csrf[NUM*KSEL];
__device__ int   d_csrs[NE];
__device__ __align__(16) __nv_bfloat16 d_xa[NUM*FDIM];
__device__ __align__(16) __nv_bfloat16 d_xb[NUM*FDIM];

typedef unsigned long long ull;

__device__ __forceinline__ float warp_sum(float v) {
#pragma unroll
    for (int o = 16; o > 0; o >>= 1) v += __shfl_xor_sync(0xffffffffu, v, o);
    return v;
}

__device__ __forceinline__ void ins4(ull& k0, ull& k1, ull& k2, ull& k3, ull c) {
    if (c < k3) {
        k3 = c;
        if (k3 < k2) { ull t = k2; k2 = k3; k3 = t; }
        if (k2 < k1) { ull t = k1; k1 = k2; k2 = t; }
        if (k1 < k0) { ull t = k0; k0 = k1; k1 = t; }
    }
}

// 1) row-normalize x + emit 2-plane bf16 split (fused)
__global__ void knorm(const float* __restrict__ x) {
    int row = blockIdx.x, t = threadIdx.x;
    float v = x[row * FDIM + t];
    float ss = warp_sum(v * v);
    __shared__ float sh[4];
    if ((t & 31) == 0) sh[t >> 5] = ss;
    __syncthreads();
    float tot = sh[0] + sh[1] + sh[2] + sh[3];
    float den = fmaxf(sqrtf(tot), 1e-8f);
    float xv = v / den;
    int i = row * FDIM + t;
    d_xn[i] = xv;
    __nv_bfloat16 a = __float2bfloat16(xv);
    d_xa[i] = a;
    d_xb[i] = __float2bfloat16(xv - __bfloat162float(a));
}

// 2) zero counters
__global__ void kinit() {
    int i = blockIdx.x * blockDim.x + threadIdx.x;
    if (i < NUM) { d_cntf[i] = 0; d_cnts[i] = 0; d_fillf[i] = 0; d_fills[i] = 0; }
}

// 3) structural in-degree
__global__ void kcnt_s(const int* __restrict__ ei) {
    int e = blockIdx.x * blockDim.x + threadIdx.x;
    if (e < NE) atomicAdd(&d_cnts[ei[NE + e]], 1);
}

// 4a) candidate generation: WMMA bf16 2-plane approx distances, 8 candidates/row.
// grid(8, 64), 256 threads, 2 CTAs/SM. Warp w owns rows rcbase + 16w .. +15.
// ct-tiles processed in two halves of 4 (c[4] accumulators) to fit 128 regs.
__global__ void __launch_bounds__(256, 2) ktopk_wmma() {
    __shared__ __align__(16) __nv_bfloat16 Bs[128 * BLDM];
    __shared__ __align__(16) float scr[8][16 * 20];
    const int g = blockIdx.y;
    const int rcbase = blockIdx.x * 128;
    const int tid = threadIdx.x, w = tid >> 5, lane = tid & 31;
    const int rowstart = rcbase + w * 16;
    const __nv_bfloat16* xa = d_xa + (size_t)g * NNODE * FDIM;
    const __nv_bfloat16* xb = d_xb + (size_t)g * NNODE * FDIM;

    wmma::fragment<wmma::matrix_a, 16, 16, 16, __nv_bfloat16, wmma::row_major> a0[8];
#pragma unroll
    for (int kt = 0; kt < 8; kt++) {
        wmma::load_matrix_sync(a0[kt], xa + (size_t)rowstart * FDIM + kt * 16, FDIM);
    }

    ull tk0 = ~0ull, tk1 = ~0ull, tk2 = ~0ull, tk3 = ~0ull;

    for (int cc = 0; cc < 8; cc++) {
        for (int h = 0; h < 2; h++) {
            wmma::fragment<wmma::accumulator, 16, 16, 16, float> c[4];
#pragma unroll
            for (int ct = 0; ct < 4; ct++) wmma::fill_fragment(c[ct], 0.0f);

            for (int pb = 0; pb < 2; pb++) {
                __syncthreads();
                {
                    const uint4* src = (const uint4*)((pb ? xb : xa) + (size_t)cc * 128 * FDIM);
                    uint4* dst = (uint4*)Bs;
                    for (int i = tid; i < 2048; i += 256) {
                        int col = i >> 4, kk = i & 15;
                        dst[col * 17 + kk] = src[i];
                    }
                }
                __syncthreads();
                if (pb == 0) {
#pragma unroll
                    for (int kt = 0; kt < 8; kt++) {
                        wmma::fragment<wmma::matrix_a, 16, 16, 16, __nv_bfloat16, wmma::row_major> a1f;
                        wmma::load_matrix_sync(a1f, xb + (size_t)rowstart * FDIM + kt * 16, FDIM);
#pragma unroll
                        for (int ct = 0; ct < 4; ct++) {
                            wmma::fragment<wmma::matrix_b, 16, 16, 16, __nv_bfloat16, wmma::col_major> b;
                            wmma::load_matrix_sync(b, Bs + (h * 4 + ct) * 16 * BLDM + kt * 16, BLDM);
                            wmma::mma_sync(c[ct], a0[kt], b, c[ct]);
                            wmma::mma_sync(c[ct], a1f, b, c[ct]);
                        }
                    }
                } else {
#pragma unroll
                    for (int kt = 0; kt < 8; kt++) {
#pragma unroll
                        for (int ct = 0; ct < 4; ct++) {
                            wmma::fragment<wmma::matrix_b, 16, 16, 16, __nv_bfloat16, wmma::col_major> b;
                            wmma::load_matrix_sync(b, Bs + (h * 4 + ct) * 16 * BLDM + kt * 16, BLDM);
                            wmma::mma_sync(c[ct], a0[kt], b, c[ct]);
                        }
                    }
                }
            }

            // extract: two lanes per row (lane r: cols lo 8, lane r+16: cols hi 8)
#pragma unroll
            for (int ct = 0; ct < 4; ct++) {
                wmma::store_matrix_sync(&scr[w][0], c[ct], 20, wmma::mem_row_major);
                __syncwarp();
                int r = lane & 15, half = lane >> 4;
                int colbase = cc * 128 + (h * 4 + ct) * 16 + half * 8;
#pragma unroll
                for (int q = 0; q < 8; q++) {
                    float s = scr[w][r * 20 + half * 8 + q];
                    float dval = 1.0f - s;
                    unsigned u = __float_as_uint(dval);
                    u = (u & 0x80000000u) ? ~u : (u | 0x80000000u);
                    ull key = (((ull)(~u)) << 10) | (ull)(colbase + q);
                    ins4(tk0, tk1, tk2, tk3, key);
                }
                __syncwarp();
            }
        }
    }

    // publish 8 candidates per row: lane r -> slots 0..3, lane r+16 -> slots 4..7
    {
        int r = lane & 15, half = lane >> 4;
        int grow = g * NNODE + rowstart + r;
        ull ks[4] = {tk0, tk1, tk2, tk3};
#pragma unroll
        for (int q = 0; q < 4; q++) {
            d_cand[grow * 8 + half * 4 + q] = g * NNODE + (int)(ks[q] & 1023ull);
        }
    }
}

// 4b) exact fp32 rescore of the 8 candidates -> final top-4 (one warp per row)
__global__ void krescore() {
    int d = (blockIdx.x * blockDim.x + threadIdx.x) >> 5;
    int lane = threadIdx.x & 31;
    const float4* xn4 = (const float4*)d_xn;
    float4 xr = xn4[d * 32 + lane];
    ull k0 = ~0ull, k1 = ~0ull, k2 = ~0ull, k3 = ~0ull;
#pragma unroll
    for (int q = 0; q < 8; q++) {
        int cand = d_cand[d * 8 + q];
        float4 y = xn4[cand * 32 + lane];
        float dot = warp_sum(xr.x * y.x + xr.y * y.y + xr.z * y.z + xr.w * y.w);
        float dval = 1.0f - dot;
        unsigned u = __float_as_uint(dval);
        u = (u & 0x80000000u) ? ~u : (u | 0x80000000u);
        ull key = (((ull)(~u)) << 10) | (ull)(cand & 1023);
        ins4(k0, k1, k2, k3, key);
    }
    if (lane == 0) {
        int gbase = d & ~(NNODE - 1);
        ull ks[4] = {k0, k1, k2, k3};
#pragma unroll
        for (int q = 0; q < 4; q++) {
            int j = (int)(ks[q] & 1023ull);
            int dg = gbase + j;
            d_topk[d * 4 + q] = dg;
            atomicAdd(&d_cntf[dg], 1);
        }
    }
}

// 5) exclusive scans (block 0 = feature counts, block 1 = structural)
__global__ void kscan() {
    int which = blockIdx.x;
    const int* cnt = which ? d_cnts : d_cntf;
    int* off = which ? d_offs : d_offf;
    __shared__ int sh[1024];
    int t = threadIdx.x;
    int base = t * 64;
    int sum = 0;
    for (int i = 0; i < 64; i++) sum += cnt[base + i];
    sh[t] = sum;
    __syncthreads();
    for (int o = 1; o < 1024; o <<= 1) {
        int v = (t >= o) ? sh[t - o] : 0;
        __syncthreads();
        sh[t] += v;
        __syncthreads();
    }
    int run = sh[t] - sum;
    for (int i = 0; i < 64; i++) { int c = cnt[base + i]; off[base + i] = run; run += c; }
}

// 6) dinv = rsqrt(deg) incl. self-loop
__global__ void kdinv() {
    int i = blockIdx.x * blockDim.x + threadIdx.x;
    if (i < NUM) {
        d_dinvf[i] = rsqrtf((float)(d_cntf[i] + 1));
        d_dinvs[i] = rsqrtf((float)(d_cnts[i] + 1));
    }
}

// 7) CSR fill
__global__ void kfill_f() {
    int e = blockIdx.x * blockDim.x + threadIdx.x;
    if (e < NUM * KSEL) {
        int srcn = e >> 2;
        int dg = d_topk[e];
        int pos = d_offf[dg] + atomicAdd(&d_fillf[dg], 1);
        d_csrf[pos] = srcn;
    }
}
__global__ void kfill_s(const int* __restrict__ ei) {
    int e = blockIdx.x * blockDim.x + threadIdx.x;
    if (e < NE) {
        int s = ei[e], dg = ei[NE + e];
        int pos = d_offs[dg] + atomicAdd(&d_fills[dg], 1);
        d_csrs[pos] = s;
    }
}

// 8) h = x @ W (z: 0=feat, 1=stru)
__global__ void __launch_bounds__(256) kgemm_h(const float* __restrict__ x,
                                               const float* __restrict__ Wf,
                                               const float* __restrict__ Wst) {
    const float* W = blockIdx.z ? Wst : Wf;
    float* out = blockIdx.z ? d_hs : d_hf;
    __shared__ __align__(16) float As[32 * 68];
    __shared__ __align__(16) float Bs[32 * 132];
    int t = threadIdx.x, tx = t & 15, ty = t >> 4;
    int rowbase = blockIdx.x * 64;
    float acc[4][8];
#pragma unroll
    for (int ri = 0; ri < 4; ri++)
#pragma unroll
        for (int ci = 0; ci < 8; ci++) acc[ri][ci] = 0.f;

    for (int kc = 0; kc < 4; kc++) {
        __syncthreads();
#pragma unroll
        for (int j = 0; j < 2; j++) {
            int idx = t + j * 256;
            int r = idx >> 3, k4 = idx & 7;
            float4 v = *(const float4*)&x[(rowbase + r) * FDIM + kc * 32 + k4 * 4];
            As[(k4 * 4 + 0) * 68 + r] = v.x; As[(k4 * 4 + 1) * 68 + r] = v.y;
            As[(k4 * 4 + 2) * 68 + r] = v.z; As[(k4 * 4 + 3) * 68 + r] = v.w;
        }
#pragma unroll
        for (int j = 0; j < 4; j++) {
            int idx = t + j * 256;
            int kk = idx >> 5, c4 = idx & 31;
            *(float4*)&Bs[kk * 132 + c4 * 4] = *(const float4*)&W[(kc * 32 + kk) * FDIM + c4 * 4];
        }
        __syncthreads();
#pragma unroll 8
        for (int k = 0; k < 32; k++) {
            float4 a  = *(const float4*)&As[k * 68 + ty * 4];
            float4 b0 = *(const float4*)&Bs[k * 132 + tx * 4];
            float4 b1 = *(const float4*)&Bs[k * 132 + 64 + tx * 4];
            float av[4] = {a.x, a.y, a.z, a.w};
            float bv[8] = {b0.x, b0.y, b0.z, b0.w, b1.x, b1.y, b1.z, b1.w};
#pragma unroll
            for (int ri = 0; ri < 4; ri++)
#pragma unroll
                for (int ci = 0; ci < 8; ci++) acc[ri][ci] += av[ri] * bv[ci];
        }
    }
#pragma unroll
    for (int ri = 0; ri < 4; ri++) {
        int row = rowbase + ty * 4 + ri;
        float4 o0 = {acc[ri][0], acc[ri][1], acc[ri][2], acc[ri][3]};
        float4 o1 = {acc[ri][4], acc[ri][5], acc[ri][6], acc[ri][7]};
        *(float4*)&out[row * FDIM + tx * 4] = o0;
        *(float4*)&out[row * FDIM + 64 + tx * 4] = o1;
    }
}

// 9) GCN aggregate + bias + relu + layernorm (one warp per node)
__global__ void kagg(int which, const float* __restrict__ bias,
                     const float* __restrict__ gamma, const float* __restrict__ beta) {
    int d = (blockIdx.x * blockDim.x + threadIdx.x) >> 5;
    int lane = threadIdx.x & 31;
    const int* off = which ? d_offs : d_offf;
    const int* cnt = which ? d_cnts : d_cntf;
    const int* csr = which ? d_csrs : d_csrf;
    const float* dinv = which ? d_dinvs : d_dinvf;
    const float4* h4 = which ? (const float4*)d_hs : (const float4*)d_hf;
    float* outp = which ? d_stru : d_feat;

    int st = off[d], n = cnt[d];
    float dd = dinv[d];
    float ax = 0.f, ay = 0.f, az = 0.f, aw = 0.f;
    int e = 0;
    for (; e + 4 <= n; e += 4) {
        int s0 = csr[st+e], s1 = csr[st+e+1], s2 = csr[st+e+2], s3 = csr[st+e+3];
        float w0 = dinv[s0]*dd, w1 = dinv[s1]*dd, w2 = dinv[s2]*dd, w3 = dinv[s3]*dd;
        float4 v0 = h4[s0*32+lane], v1 = h4[s1*32+lane];
        float4 v2 = h4[s2*32+lane], v3 = h4[s3*32+lane];
        ax += v0.x*w0 + v1.x*w1 + v2.x*w2 + v3.x*w3;
        ay += v0.y*w0 + v1.y*w1 + v2.y*w2 + v3.y*w3;
        az += v0.z*w0 + v1.z*w1 + v2.z*w2 + v3.z*w3;
        aw += v0.w*w0 + v1.w*w1 + v2.w*w2 + v3.w*w3;
    }
    for (; e < n; e++) {
        int s = csr[st + e];
        float wg = dinv[s] * dd;
        float4 v = h4[s*32+lane];
        ax += v.x*wg; ay += v.y*wg; az += v.z*wg; aw += v.w*wg;
    }
    {
        float4 v = h4[d*32+lane];
        float wg = dd * dd;
        ax += v.x*wg; ay += v.y*wg; az += v.z*wg; aw += v.w*wg;
    }
    float4 b4 = ((const float4*)bias)[lane];
    ax = fmaxf(ax + b4.x, 0.f); ay = fmaxf(ay + b4.y, 0.f);
    az = fmaxf(az + b4.z, 0.f); aw = fmaxf(aw + b4.w, 0.f);
    float mean = warp_sum(ax + ay + az + aw) * (1.0f / 128.0f);
    float dx = ax - mean, dy = ay - mean, dz = az - mean, dw = aw - mean;
    float var = warp_sum(dx*dx + dy*dy + dz*dz + dw*dw) * (1.0f / 128.0f);
    float rs = rsqrtf(var + 1e-5f);
    float4 g4 = ((const float4*)gamma)[lane], e4 = ((const float4*)beta)[lane];
    float4 o = {dx*rs*g4.x + e4.x, dy*rs*g4.y + e4.y,
                dz*rs*g4.z + e4.z, dw*rs*g4.w + e4.w};
    ((float4*)outp)[d*32+lane] = o;
}

// 10) gate = sigmoid([feat|stru] @ W_gate + b_gate)
__global__ void __launch_bounds__(256) kgemm_gate(const float* __restrict__ Wg,
                                                  const float* __restrict__ bg) {
    __shared__ __align__(16) float As[32 * 68];
    __shared__ __align__(16) float Bs[32 * 132];
    int t = threadIdx.x, tx = t & 15, ty = t >> 4;
    int rowbase = blockIdx.x * 64;
    float acc[4][8];
#pragma unroll
    for (int ri = 0; ri < 4; ri++)
#pragma unroll
        for (int ci = 0; ci < 8; ci++) acc[ri][ci] = 0.f;

    for (int kc = 0; kc < 8; kc++) {
        const float* Asrc = (kc < 4) ? d_feat : d_stru;
        int kcol = (kc & 3) * 32;
        __syncthreads();
#pragma unroll
        for (int j = 0; j < 2; j++) {
            int idx = t + j * 256;
            int r = idx >> 3, k4 = idx & 7;
            float4 v = *(const float4*)&Asrc[(rowbase + r) * FDIM + kcol + k4 * 4];
            As[(k4 * 4 + 0) * 68 + r] = v.x; As[(k4 * 4 + 1) * 68 + r] = v.y;
            As[(k4 * 4 + 2) * 68 + r] = v.z; As[(k4 * 4 + 3) * 68 + r] = v.w;
        }
#pragma unroll
        for (int j = 0; j < 4; j++) {
            int idx = t + j * 256;
            int kk = idx >> 5, c4 = idx & 31;
            *(float4*)&Bs[kk * 132 + c4 * 4] = *(const float4*)&Wg[(kc * 32 + kk) * FDIM + c4 * 4];
        }
        __syncthreads();
#pragma unroll 8
        for (int k = 0; k < 32; k++) {
            float4 a  = *(const float4*)&As[k * 68 + ty * 4];
            float4 b0 = *(const float4*)&Bs[k * 132 + tx * 4];
            float4 b1 = *(const float4*)&Bs[k * 132 + 64 + tx * 4];
            float av[4] = {a.x, a.y, a.z, a.w};
            float bv[8] = {b0.x, b0.y, b0.z, b0.w, b1.x, b1.y, b1.z, b1.w};
#pragma unroll
            for (int ri = 0; ri < 4; ri++)
#pragma unroll
                for (int ci = 0; ci < 8; ci++) acc[ri][ci] += av[ri] * bv[ci];
        }
    }
    float bgv[8];
#pragma unroll
    for (int ci = 0; ci < 8; ci++)
        bgv[ci] = bg[(ci < 4) ? (tx * 4 + ci) : (64 + tx * 4 + ci - 4)];
#pragma unroll
    for (int ri = 0; ri < 4; ri++) {
        int row = rowbase + ty * 4 + ri;
#pragma unroll
        for (int ci = 0; ci < 8; ci++) {
            int col = (ci < 4) ? (tx * 4 + ci) : (64 + tx * 4 + ci - 4);
            float z = acc[ri][ci] + bgv[ci];
            d_gate[row * FDIM + col] = 1.0f / (1.0f + expf(-z));
        }
    }
}

// 11) fuse + layernorm + residual
__global__ void kfinal(const float* __restrict__ x, const float* __restrict__ gamma,
                       const float* __restrict__ beta, float* __restrict__ out) {
    int d = (blockIdx.x * blockDim.x + threadIdx.x) >> 5;
    int lane = threadIdx.x & 31;
    float4 f = ((const float4*)d_feat)[d*32+lane];
    float4 s = ((const float4*)d_stru)[d*32+lane];
    float4 g = ((const float4*)d_gate)[d*32+lane];
    float4 xv = ((const float4*)x)[d*32+lane];
    float fx = g.x*f.x + (1.f-g.x)*s.x;
    float fy = g.y*f.y + (1.f-g.y)*s.y;
    float fz = g.z*f.z + (1.f-g.z)*s.z;
    float fw = g.w*f.w + (1.f-g.w)*s.w;
    float mean = warp_sum(fx + fy + fz + fw) * (1.0f / 128.0f);
    float dx = fx-mean, dy = fy-mean, dz = fz-mean, dw = fw-mean;
    float var = warp_sum(dx*dx + dy*dy + dz*dz + dw*dw) * (1.0f / 128.0f);
    float rs = rsqrtf(var + 1e-5f);
    float4 g4 = ((const float4*)gamma)[lane], b4 = ((const float4*)beta)[lane];
    float4 o = {dx*rs*g4.x + b4.x + xv.x, dy*rs*g4.y + b4.y + xv.y,
                dz*rs*g4.z + b4.z + xv.z, dw*rs*g4.w + b4.w + xv.w};
    ((float4*)out)[d*32+lane] = o;
}

extern "C" void kernel_launch(void* const* d_in, const int* in_sizes, int n_in,
                              void* d_out, int out_size) {
    const float* x      = (const float*)d_in[0];
    const int*   ei     = (const int*)  d_in[1];
    const float* W_feat = (const float*)d_in[2];
    const float* b_feat = (const float*)d_in[3];
    const float* W_stru = (const float*)d_in[4];
    const float* b_stru = (const float*)d_in[5];
    const float* W_gate = (const float*)d_in[6];
    const float* b_gate = (const float*)d_in[7];
    const float* g_feat = (const float*)d_in[8];
    const float* be_feat= (const float*)d_in[9];
    const float* g_stru = (const float*)d_in[10];
    const float* be_stru= (const float*)d_in[11];
    const float* g_fus  = (const float*)d_in[12];
    const float* be_fus = (const float*)d_in[13];
    float* out = (float*)d_out;

    knorm<<<NUM, 128>>>(x);
    kinit<<<NUM / 256, 256>>>();
    kcnt_s<<<NE / 256, 256>>>(ei);
    ktopk_wmma<<<dim3(8, 64), 256>>>();
    krescore<<<(NUM * 32) / 256, 256>>>();
    kgemm_h<<<dim3(NUM / 64, 1, 2), 256>>>(x, W_feat, W_stru);
    kscan<<<2, 1024>>>();
    kdinv<<<NUM / 256, 256>>>();
    kfill_f<<<(NUM * KSEL) / 256, 256>>>();
    kfill_s<<<NE / 256, 256>>>(ei);
    kagg<<<(NUM * 32) / 256, 256>>>(0, b_feat, g_feat, be_feat);
    kagg<<<(NUM * 32) / 256, 256>>>(1, b_stru, g_stru, be_stru);
    kgemm_gate<<<NUM / 64, 256>>>(W_gate, b_gate);
    kfinal<<<(NUM * 32) / 256, 256>>>(x, g_fus, be_fus, out);
}